// round 6
// baseline (speedup 1.0000x reference)
#include <cuda_runtime.h>
#include <math.h>

#define BS 8
#define CC 256
#define NN 1500
#define HH 8
#define DK 32

typedef unsigned long long ull;

// ---------------- f32x2 packed helpers (Blackwell) ---------------------------
__device__ __forceinline__ ull pk2(float lo, float hi) {
    ull r;
    asm("mov.b64 %0, {%1, %2};" : "=l"(r)
        : "r"(__float_as_uint(lo)), "r"(__float_as_uint(hi)));
    return r;
}
__device__ __forceinline__ ull fma2(ull a, ull b, ull c) {
    ull d;
    asm("fma.rn.f32x2 %0, %1, %2, %3;" : "=l"(d) : "l"(a), "l"(b), "l"(c));
    return d;
}
__device__ __forceinline__ void unpk2(ull v, float& lo, float& hi) {
    unsigned ulo, uhi;
    asm("mov.b64 {%0, %1}, %2;" : "=r"(ulo), "=r"(uhi) : "l"(v));
    lo = __uint_as_float(ulo); hi = __uint_as_float(uhi);
}

// ---------------- scratch (static device globals; no allocs) ----------------
// q/k/v stored head-interleaved: [b][n][h*DK]  (256 floats per token row)
__device__ float g_q[(size_t)BS * NN * CC];
__device__ float g_k[(size_t)BS * NN * CC];
__device__ float g_v[(size_t)BS * NN * CC];
__device__ float g_val[(size_t)BS * NN * CC];              // [b][n][c]
__device__ unsigned short g_nbr[(size_t)BS * NN * NN];     // per-row neighbor j lists
__device__ int g_cnt[BS * NN];
__device__ int g_perm[BS * NN];                            // spatial-sorted order

// ---------------- 0) spatial counting sort (per batch) ----------------------
__global__ __launch_bounds__(256) void sort_kernel(const float* __restrict__ boxes) {
    __shared__ int hist[64], offs[64];
    int b = blockIdx.x;
    int t = threadIdx.x;
    if (t < 64) hist[t] = 0;
    __syncthreads();
    const float4* bb = (const float4*)(boxes + (size_t)b * NN * 4);
    for (int n = t; n < NN; n += 256) {
        float4 bx = bb[n];
        int kx = min(7, max(0, (int)(bx.x * 8.0f)));
        int ky = min(7, max(0, (int)(bx.y * 8.0f)));
        atomicAdd(&hist[kx * 8 + ky], 1);
    }
    __syncthreads();
    if (t == 0) {
        int run = 0;
        for (int k = 0; k < 64; k++) { offs[k] = run; run += hist[k]; }
    }
    __syncthreads();
    for (int n = t; n < NN; n += 256) {
        float4 bx = bb[n];
        int kx = min(7, max(0, (int)(bx.x * 8.0f)));
        int ky = min(7, max(0, (int)(bx.y * 8.0f)));
        int pos = atomicAdd(&offs[kx * 8 + ky], 1);
        g_perm[b * NN + pos] = n;
    }
}

// ---------------- 1) mask + neighbor-list build ------------------------------
// 32 queries per block (warp handles 4) to amortize the shared-memory fill.
__global__ __launch_bounds__(256) void mask_kernel(const float* __restrict__ boxes,
                                                   const float* __restrict__ cm) {
    __shared__ float sx1[NN], sy1[NN], sx2[NN], sy2[NN], sa[NN], scm[NN];
    int b = blockIdx.y;
    const float4* bb = (const float4*)(boxes + (size_t)b * NN * 4);
    for (int idx = threadIdx.x; idx < NN; idx += blockDim.x) {
        float4 bx = bb[idx];                  // cx, cy, w, h
        float x1 = bx.x - 0.5f * bx.z;
        float x2 = bx.x + 0.5f * bx.z;
        float y1 = bx.y - 0.5f * bx.w;
        float y2 = bx.y + 0.5f * bx.w;
        sx1[idx] = x1; sx2[idx] = x2; sy1[idx] = y1; sy2[idx] = y2;
        sa[idx] = (x2 - x1) * (y2 - y1);
        scm[idx] = cm[(size_t)b * NN + idx];
    }
    __syncthreads();

    int warp = threadIdx.x >> 5, lane = threadIdx.x & 31;
    for (int qi = 0; qi < 4; qi++) {
        int i = blockIdx.x * 32 + warp * 4 + qi;
        if (i >= NN) break;
        float x1i = sx1[i], x2i = sx2[i], y1i = sy1[i], y2i = sy2[i];
        float ai = sa[i], cmi = scm[i];
        unsigned short* out = g_nbr + ((size_t)b * NN + i) * NN;
        int cnt = 0;
        for (int jb = 0; jb < NN; jb += 32) {
            int j = jb + lane;
            bool nb = false;
            if (j < NN) {
                float ltx = fmaxf(x1i, sx1[j]);
                float lty = fmaxf(y1i, sy1[j]);
                float rbx = fminf(x2i, sx2[j]);
                float rby = fminf(y2i, sy2[j]);
                float iw = fmaxf(rbx - ltx, 0.0f);
                float ih = fmaxf(rby - lty, 0.0f);
                float inter = iw * ih;
                float uni = (ai + sa[j]) - inter;
                float prod = cmi * scm[j];
                if (prod == 1.0f) {
                    // exact predicate for fl_RN(inter/uni) > 0.5 w/o dividing
                    float i2 = inter + inter;
                    if (i2 > uni * 1.00001f) nb = true;
                    else if (i2 < uni * 0.99999f) nb = false;
                    else nb = ((double)inter >
                               (double)uni * 0.5000000298023223876953125);
                } else {
                    float iou = __fdiv_rn(inter, uni);
                    nb = (iou * prod) > 0.5f;
                }
            }
            unsigned bal = __ballot_sync(0xffffffffu, nb);
            int pos = cnt + __popc(bal & ((1u << lane) - 1u));
            if (nb) out[pos] = (unsigned short)j;
            cnt += __popc(bal);
        }
        if (lane == 0) g_cnt[b * NN + i] = cnt;
    }
}

// ---------------- 2) QKV head projections (head-interleaved output) ---------
__global__ __launch_bounds__(256) void qkv_kernel(const float* __restrict__ qin,
                                                  const float* __restrict__ kin,
                                                  const float* __restrict__ vin,
                                                  const float* __restrict__ wq,
                                                  const float* __restrict__ wk,
                                                  const float* __restrict__ wv) {
    __shared__ float4 sw[256];   // 32x32 weight matrix for this (mat, h)
    int mat = blockIdx.z;
    int bh = blockIdx.y;
    int b = bh >> 3, h = bh & 7;
    const float* W = (mat == 0 ? wq : (mat == 1 ? wk : wv)) + h * DK * DK;
    const float* X = (mat == 0 ? qin : (mat == 1 ? kin : vin));
    float* O = (mat == 0 ? g_q : (mat == 1 ? g_k : g_v));
    sw[threadIdx.x] = ((const float4*)W)[threadIdx.x];
    __syncthreads();

    int i = blockIdx.x * 256 + threadIdx.x;
    if (i >= NN) return;
    float x[DK];
    const float* xp = X + ((size_t)b * CC + h * DK) * NN + i;
#pragma unroll
    for (int j = 0; j < DK; j++) x[j] = xp[(size_t)j * NN];

    float out[DK];
#pragma unroll
    for (int d = 0; d < DK; d++) {
        float acc = 0.0f;
#pragma unroll
        for (int jq = 0; jq < 8; jq++) {
            float4 w4 = sw[d * 8 + jq];
            acc = fmaf(w4.x, x[jq * 4 + 0], acc);
            acc = fmaf(w4.y, x[jq * 4 + 1], acc);
            acc = fmaf(w4.z, x[jq * 4 + 2], acc);
            acc = fmaf(w4.w, x[jq * 4 + 3], acc);
        }
        out[d] = acc;
    }
    float4* op = (float4*)(O + ((size_t)b * NN + i) * CC + h * DK);
#pragma unroll
    for (int r = 0; r < 8; r++)
        op[r] = make_float4(out[r * 4], out[r * 4 + 1], out[r * 4 + 2], out[r * 4 + 3]);
}

// ---------------- 3) sparse masked attention (warp per query, ALL heads) ----
// No register double-buffer (lean regs -> high occupancy hides load latency).
__global__ __launch_bounds__(256, 3) void attn_kernel() {
    int warp = threadIdx.x >> 5, lane = threadIdx.x & 31;
    int c = lane & 3;
    int gs = blockIdx.x * 8 + warp;          // sorted rank within b*NN
    if (gs >= BS * NN) return;
    int b = gs / NN;
    int gi = b * NN + g_perm[gs];            // actual b*NN + i

    int cnt = g_cnt[gi];
    int off = (lane >> 2) * DK + c * 8;      // this lane's 8-dim slice
    const float* vbase = g_v + (size_t)b * NN * CC;
    float* valp = g_val + (size_t)gi * CC + off;
    int i_local = gi - b * NN;

    if (cnt == 0) {   // has_nb == 0 fallback: val = v
        const float4* vr = (const float4*)(vbase + (size_t)i_local * CC + off);
        float4 v0 = vr[0], v1 = vr[1];
        ((float4*)valp)[0] = v0;
        ((float4*)valp)[1] = v1;
        return;
    }

    const float4* qp = (const float4*)(g_q + (size_t)gi * CC + off);
    float4 qa = qp[0], qb = qp[1];
    const unsigned short* nb = g_nbr + (size_t)gi * NN;
    const float* kbase = g_k + (size_t)b * NN * CC;
    int cm1 = cnt - 1;

    // reference: max_val = max(attn * mask) -> masked zeros participate in max
    float minit = (cnt < NN) ? 0.0f : -INFINITY;
    float mA = minit, mB = minit, lA = 0.f, lB = 0.f;
    float4 oAa = {0,0,0,0}, oAb = {0,0,0,0}, oBa = {0,0,0,0}, oBb = {0,0,0,0};

    for (int t = 0; t < cnt; t += 2) {
        int jA = nb[t], jB = nb[min(t + 1, cm1)];
        const float4* kpA = (const float4*)(kbase + (size_t)jA * CC + off);
        const float4* vpA = (const float4*)(vbase + (size_t)jA * CC + off);
        const float4* kpB = (const float4*)(kbase + (size_t)jB * CC + off);
        const float4* vpB = (const float4*)(vbase + (size_t)jB * CC + off);
        float4 kAa = kpA[0], kAb = kpA[1], vAa = vpA[0], vAb = vpA[1];
        float4 kBa = kpB[0], kBb = kpB[1], vBa = vpB[0], vBb = vpB[1];

        // stream A (t < cnt always)
        float sA = qa.x * kAa.x + qa.y * kAa.y + qa.z * kAa.z + qa.w * kAa.w
                 + qb.x * kAb.x + qb.y * kAb.y + qb.z * kAb.z + qb.w * kAb.w;
        sA += __shfl_xor_sync(0xffffffffu, sA, 1);
        sA += __shfl_xor_sync(0xffffffffu, sA, 2);
        float mnA = fmaxf(mA, sA);
        float scA = __expf(mA - mnA);
        float pA = __expf(sA - mnA);
        lA = lA * scA + pA;
        oAa.x = fmaf(pA, vAa.x, oAa.x * scA); oAa.y = fmaf(pA, vAa.y, oAa.y * scA);
        oAa.z = fmaf(pA, vAa.z, oAa.z * scA); oAa.w = fmaf(pA, vAa.w, oAa.w * scA);
        oAb.x = fmaf(pA, vAb.x, oAb.x * scA); oAb.y = fmaf(pA, vAb.y, oAb.y * scA);
        oAb.z = fmaf(pA, vAb.z, oAb.z * scA); oAb.w = fmaf(pA, vAb.w, oAb.w * scA);
        mA = mnA;

        // stream B (t+1 may be past the end)
        float sB = qa.x * kBa.x + qa.y * kBa.y + qa.z * kBa.z + qa.w * kBa.w
                 + qb.x * kBb.x + qb.y * kBb.y + qb.z * kBb.z + qb.w * kBb.w;
        sB += __shfl_xor_sync(0xffffffffu, sB, 1);
        sB += __shfl_xor_sync(0xffffffffu, sB, 2);
        if (t + 1 >= cnt) sB = -INFINITY;
        float mnB = fmaxf(mB, sB);
        float scB = __expf(mB - mnB);
        float pB = __expf(sB - mnB);          // exp(-inf)=0 for padding
        lB = lB * scB + pB;
        oBa.x = fmaf(pB, vBa.x, oBa.x * scB); oBa.y = fmaf(pB, vBa.y, oBa.y * scB);
        oBa.z = fmaf(pB, vBa.z, oBa.z * scB); oBa.w = fmaf(pB, vBa.w, oBa.w * scB);
        oBb.x = fmaf(pB, vBb.x, oBb.x * scB); oBb.y = fmaf(pB, vBb.y, oBb.y * scB);
        oBb.z = fmaf(pB, vBb.z, oBb.z * scB); oBb.w = fmaf(pB, vBb.w, oBb.w * scB);
        mB = mnB;
    }

    // merge the two streams locally
    float m = fmaxf(mA, mB);
    float eA = __expf(mA - m), eB = __expf(mB - m);
    float l = lA * eA + lB * eB;
    float inv = 1.0f / (l + 1e-8f);
    float4 ra, rb;
    ra.x = (oAa.x * eA + oBa.x * eB) * inv; ra.y = (oAa.y * eA + oBa.y * eB) * inv;
    ra.z = (oAa.z * eA + oBa.z * eB) * inv; ra.w = (oAa.w * eA + oBa.w * eB) * inv;
    rb.x = (oAb.x * eA + oBb.x * eB) * inv; rb.y = (oAb.y * eA + oBb.y * eB) * inv;
    rb.z = (oAb.z * eA + oBb.z * eB) * inv; rb.w = (oAb.w * eA + oBb.w * eB) * inv;
    ((float4*)valp)[0] = ra;
    ((float4*)valp)[1] = rb;
}

// ---------------- 4) output projection  out = Wp @ val + b ------------------
// FFMA2 v2: f32x2 pairs span TWO ADJACENT co, so W pairs are a free 64-bit
// reinterpret of the float smem row; only V is (v,v)-duplicated (at fill time).
// 256 threads, 128co x 128i tile, KC=16, no register prefetch; grid = 192
// blocks = one fully-resident wave (2 blocks/SM).
#define QCO 128
#define QIT 128
#define QKC 16
__global__ __launch_bounds__(256, 2) void proj_kernel(const float* __restrict__ wp,
                                                      const float* __restrict__ bp,
                                                      float* __restrict__ out) {
    __shared__ float Ws[QKC][QCO + 4];    // [ci][co]   (row 528B, 16B-aligned)
    __shared__ ull  Vs2[QKC][QIT + 2];    // [ci][i] dup pairs (row 1040B)
    int b = blockIdx.z;
    int coT = blockIdx.y * QCO;
    int iT = blockIdx.x * QIT;
    int t = threadIdx.x;
    int tx = t & 15;                   // i group: {tx*2+1? } 4 segs of 2 at s*32
    int ty = t >> 4;                   // co group: 8 consecutive co at ty*8
    int cix = (t & 3) * 4;             // fill: ci quad
    int rr = t >> 2;                   // fill: row 0..63

    ull acc2[4][8];
#pragma unroll
    for (int cp = 0; cp < 4; cp++)
#pragma unroll
        for (int e = 0; e < 8; e++) acc2[cp][e] = 0ull;

    for (int kc = 0; kc < CC; kc += QKC) {
        // fill Ws (natural float layout)
#pragma unroll
        for (int p = 0; p < 2; p++) {
            int r = rr + p * 64;
            float4 w = *(const float4*)&wp[(size_t)(coT + r) * CC + kc + cix];
            Ws[cix + 0][r] = w.x; Ws[cix + 1][r] = w.y;
            Ws[cix + 2][r] = w.z; Ws[cix + 3][r] = w.w;
        }
        // fill Vs2 (duplicated pairs)
#pragma unroll
        for (int p = 0; p < 2; p++) {
            int i = rr + p * 64;
            int gi = iT + i;
            float4 v = (gi < NN) ? *(const float4*)&g_val[((size_t)b * NN + gi) * CC + kc + cix]
                                 : make_float4(0.f, 0.f, 0.f, 0.f);
            Vs2[cix + 0][i] = pk2(v.x, v.x); Vs2[cix + 1][i] = pk2(v.y, v.y);
            Vs2[cix + 2][i] = pk2(v.z, v.z); Vs2[cix + 3][i] = pk2(v.w, v.w);
        }
        __syncthreads();

#pragma unroll
        for (int ci = 0; ci < QKC; ci++) {
            // W pairs: reinterpret consecutive floats as (w[co], w[co+1])
            ulonglong2 wA = *(const ulonglong2*)&Ws[ci][ty * 8];
            ulonglong2 wB = *(const ulonglong2*)&Ws[ci][ty * 8 + 4];
            ull wr[4] = {wA.x, wA.y, wB.x, wB.y};
            ull vr[8];
#pragma unroll
            for (int s = 0; s < 4; s++) {
                ulonglong2 vv = *(const ulonglong2*)&Vs2[ci][s * 32 + tx * 2];
                vr[2 * s] = vv.x; vr[2 * s + 1] = vv.y;
            }
#pragma unroll
            for (int cp = 0; cp < 4; cp++)
#pragma unroll
                for (int e = 0; e < 8; e++)
                    acc2[cp][e] = fma2(wr[cp], vr[e], acc2[cp][e]);
        }
        __syncthreads();
    }

    // epilogue: unpack (co, co+1) pairs, add bias, store float2 per i-pair
#pragma unroll
    for (int cp = 0; cp < 4; cp++) {
        int co0 = coT + ty * 8 + cp * 2;
        float a0[8], a1[8];
#pragma unroll
        for (int e = 0; e < 8; e++) unpk2(acc2[cp][e], a0[e], a1[e]);
        float b0 = bp[co0], b1 = bp[co0 + 1];
#pragma unroll
        for (int s = 0; s < 4; s++) {
            int gi = iT + s * 32 + tx * 2;
            if (gi < NN) {   // NN even -> pair fully valid
                float2 r0 = make_float2(a0[2 * s] + b0, a0[2 * s + 1] + b0);
                float2 r1 = make_float2(a1[2 * s] + b1, a1[2 * s + 1] + b1);
                *(float2*)&out[((size_t)b * CC + co0) * NN + gi] = r0;
                *(float2*)&out[((size_t)b * CC + co0 + 1) * NN + gi] = r1;
            }
        }
    }
}

// ---------------- launch ----------------------------------------------------
extern "C" void kernel_launch(void* const* d_in, const int* in_sizes, int n_in,
                              void* d_out, int out_size) {
    const float* queries = (const float*)d_in[0];
    const float* keys    = (const float*)d_in[1];
    const float* values  = (const float*)d_in[2];
    const float* boxes   = (const float*)d_in[3];
    const float* curmask = (const float*)d_in[4];
    const float* wq      = (const float*)d_in[5];
    const float* wk      = (const float*)d_in[6];
    const float* wv      = (const float*)d_in[7];
    const float* w_proj  = (const float*)d_in[8];
    const float* b_proj  = (const float*)d_in[9];
    float* out = (float*)d_out;

    sort_kernel<<<BS, 256>>>(boxes);
    mask_kernel<<<dim3(47, BS), 256>>>(boxes, curmask);
    qkv_kernel<<<dim3(6, BS * HH, 3), 256>>>(queries, keys, values, wq, wk, wv);
    attn_kernel<<<dim3((BS * NN + 7) / 8), 256>>>();
    proj_kernel<<<dim3((NN + QIT - 1) / QIT, CC / QCO, BS), 256>>>(w_proj, b_proj, out);
}

// round 7
// speedup vs baseline: 1.1512x; 1.1512x over previous
#include <cuda_runtime.h>
#include <math.h>

#define BS 8
#define CC 256
#define NN 1500
#define HH 8
#define DK 32

// ---------------- scratch (static device globals; no allocs) ----------------
// q/k/v stored head-interleaved: [b][n][h*DK]  (256 floats per token row)
__device__ float g_q[(size_t)BS * NN * CC];
__device__ float g_k[(size_t)BS * NN * CC];
__device__ float g_v[(size_t)BS * NN * CC];
__device__ float g_val[(size_t)BS * NN * CC];              // [b][n][c]
__device__ unsigned short g_nbr[(size_t)BS * NN * NN];     // per-row neighbor j lists
__device__ int g_cnt[BS * NN];
__device__ int g_perm[BS * NN];                            // spatial-sorted order

// ---------------- 0) spatial counting sort (per batch) ----------------------
__global__ __launch_bounds__(256) void sort_kernel(const float* __restrict__ boxes) {
    __shared__ int hist[64], offs[64];
    int b = blockIdx.x;
    int t = threadIdx.x;
    if (t < 64) hist[t] = 0;
    __syncthreads();
    const float4* bb = (const float4*)(boxes + (size_t)b * NN * 4);
    for (int n = t; n < NN; n += 256) {
        float4 bx = bb[n];
        int kx = min(7, max(0, (int)(bx.x * 8.0f)));
        int ky = min(7, max(0, (int)(bx.y * 8.0f)));
        atomicAdd(&hist[kx * 8 + ky], 1);
    }
    __syncthreads();
    if (t == 0) {
        int run = 0;
        for (int k = 0; k < 64; k++) { offs[k] = run; run += hist[k]; }
    }
    __syncthreads();
    for (int n = t; n < NN; n += 256) {
        float4 bx = bb[n];
        int kx = min(7, max(0, (int)(bx.x * 8.0f)));
        int ky = min(7, max(0, (int)(bx.y * 8.0f)));
        int pos = atomicAdd(&offs[kx * 8 + ky], 1);
        g_perm[b * NN + pos] = n;
    }
}

// ---------------- 1) mask + neighbor-list build (warp per query) -------------
__global__ __launch_bounds__(256) void mask_kernel(const float* __restrict__ boxes,
                                                   const float* __restrict__ cm) {
    __shared__ float sx1[NN], sy1[NN], sx2[NN], sy2[NN], sa[NN], scm[NN];
    int b = blockIdx.y;
    const float4* bb = (const float4*)(boxes + (size_t)b * NN * 4);
    for (int idx = threadIdx.x; idx < NN; idx += blockDim.x) {
        float4 bx = bb[idx];                  // cx, cy, w, h
        float x1 = bx.x - 0.5f * bx.z;
        float x2 = bx.x + 0.5f * bx.z;
        float y1 = bx.y - 0.5f * bx.w;
        float y2 = bx.y + 0.5f * bx.w;
        sx1[idx] = x1; sx2[idx] = x2; sy1[idx] = y1; sy2[idx] = y2;
        sa[idx] = (x2 - x1) * (y2 - y1);
        scm[idx] = cm[(size_t)b * NN + idx];
    }
    __syncthreads();

    int warp = threadIdx.x >> 5, lane = threadIdx.x & 31;
    int i = blockIdx.x * 8 + warp;
    if (i >= NN) return;
    float x1i = sx1[i], x2i = sx2[i], y1i = sy1[i], y2i = sy2[i];
    float ai = sa[i], cmi = scm[i];
    unsigned short* out = g_nbr + ((size_t)b * NN + i) * NN;
    int cnt = 0;
    for (int jb = 0; jb < NN; jb += 32) {
        int j = jb + lane;
        bool nb = false;
        if (j < NN) {
            float ltx = fmaxf(x1i, sx1[j]);
            float lty = fmaxf(y1i, sy1[j]);
            float rbx = fminf(x2i, sx2[j]);
            float rby = fminf(y2i, sy2[j]);
            float iw = fmaxf(rbx - ltx, 0.0f);
            float ih = fmaxf(rby - lty, 0.0f);
            float inter = iw * ih;
            float uni = (ai + sa[j]) - inter;
            float prod = cmi * scm[j];
            if (prod == 1.0f) {
                // exact predicate for fl_RN(inter/uni) > 0.5 without dividing
                float i2 = inter + inter;
                if (i2 > uni * 1.00001f) nb = true;
                else if (i2 < uni * 0.99999f) nb = false;
                else nb = ((double)inter >
                           (double)uni * 0.5000000298023223876953125);
                // uni==0 -> all compares false -> matches NaN>0.5 == false
            } else {
                float iou = __fdiv_rn(inter, uni);
                nb = (iou * prod) > 0.5f;
            }
        }
        unsigned bal = __ballot_sync(0xffffffffu, nb);
        int pos = cnt + __popc(bal & ((1u << lane) - 1u));
        if (nb) out[pos] = (unsigned short)j;
        cnt += __popc(bal);
    }
    if (lane == 0) g_cnt[b * NN + i] = cnt;
}

// ---------------- 2) QKV head projections (head-interleaved output) ---------
__global__ __launch_bounds__(256) void qkv_kernel(const float* __restrict__ qin,
                                                  const float* __restrict__ kin,
                                                  const float* __restrict__ vin,
                                                  const float* __restrict__ wq,
                                                  const float* __restrict__ wk,
                                                  const float* __restrict__ wv) {
    __shared__ float4 sw[256];   // 32x32 weight matrix for this (mat, h)
    int mat = blockIdx.z;
    int bh = blockIdx.y;
    int b = bh >> 3, h = bh & 7;
    const float* W = (mat == 0 ? wq : (mat == 1 ? wk : wv)) + h * DK * DK;
    const float* X = (mat == 0 ? qin : (mat == 1 ? kin : vin));
    float* O = (mat == 0 ? g_q : (mat == 1 ? g_k : g_v));
    sw[threadIdx.x] = ((const float4*)W)[threadIdx.x];
    __syncthreads();

    int i = blockIdx.x * 256 + threadIdx.x;
    if (i >= NN) return;
    float x[DK];
    const float* xp = X + ((size_t)b * CC + h * DK) * NN + i;
#pragma unroll
    for (int j = 0; j < DK; j++) x[j] = xp[(size_t)j * NN];

    float out[DK];
#pragma unroll
    for (int d = 0; d < DK; d++) {
        float acc = 0.0f;
#pragma unroll
        for (int jq = 0; jq < 8; jq++) {
            float4 w4 = sw[d * 8 + jq];
            acc = fmaf(w4.x, x[jq * 4 + 0], acc);
            acc = fmaf(w4.y, x[jq * 4 + 1], acc);
            acc = fmaf(w4.z, x[jq * 4 + 2], acc);
            acc = fmaf(w4.w, x[jq * 4 + 3], acc);
        }
        out[d] = acc;
    }
    float4* op = (float4*)(O + ((size_t)b * NN + i) * CC + h * DK);
#pragma unroll
    for (int r = 0; r < 8; r++)
        op[r] = make_float4(out[r * 4], out[r * 4 + 1], out[r * 4 + 2], out[r * 4 + 3]);
}

// ---------------- 3) sparse masked attention (warp per query, ALL heads) ----
// 128-thread blocks (4 queries) for fine-grained scheduling against the high
// variance in per-query neighbor count. Lean registers -> 24 warps/SM.
__global__ __launch_bounds__(128) void attn_kernel() {
    int warp = threadIdx.x >> 5, lane = threadIdx.x & 31;
    int c = lane & 3;
    int gs = blockIdx.x * 4 + warp;          // sorted rank within b*NN
    if (gs >= BS * NN) return;
    int b = gs / NN;
    int gi = b * NN + g_perm[gs];            // actual b*NN + i

    int cnt = g_cnt[gi];
    int off = (lane >> 2) * DK + c * 8;      // this lane's 8-dim slice
    const float* vbase = g_v + (size_t)b * NN * CC;
    float* valp = g_val + (size_t)gi * CC + off;
    int i_local = gi - b * NN;

    if (cnt == 0) {   // has_nb == 0 fallback: val = v
        const float4* vr = (const float4*)(vbase + (size_t)i_local * CC + off);
        float4 v0 = vr[0], v1 = vr[1];
        ((float4*)valp)[0] = v0;
        ((float4*)valp)[1] = v1;
        return;
    }

    const float4* qp = (const float4*)(g_q + (size_t)gi * CC + off);
    float4 qa = qp[0], qb = qp[1];
    const unsigned short* nb = g_nbr + (size_t)gi * NN;
    const float* kbase = g_k + (size_t)b * NN * CC;
    int cm1 = cnt - 1;

    // reference: max_val = max(attn * mask) -> masked zeros participate in max
    float minit = (cnt < NN) ? 0.0f : -INFINITY;
    float mA = minit, mB = minit, lA = 0.f, lB = 0.f;
    float4 oAa = {0,0,0,0}, oAb = {0,0,0,0}, oBa = {0,0,0,0}, oBb = {0,0,0,0};

    for (int t = 0; t < cnt; t += 2) {
        int jA = nb[t], jB = nb[min(t + 1, cm1)];
        const float4* kpA = (const float4*)(kbase + (size_t)jA * CC + off);
        const float4* vpA = (const float4*)(vbase + (size_t)jA * CC + off);
        const float4* kpB = (const float4*)(kbase + (size_t)jB * CC + off);
        const float4* vpB = (const float4*)(vbase + (size_t)jB * CC + off);
        float4 kAa = kpA[0], kAb = kpA[1], vAa = vpA[0], vAb = vpA[1];
        float4 kBa = kpB[0], kBb = kpB[1], vBa = vpB[0], vBb = vpB[1];

        // stream A (t < cnt always)
        float sA = qa.x * kAa.x + qa.y * kAa.y + qa.z * kAa.z + qa.w * kAa.w
                 + qb.x * kAb.x + qb.y * kAb.y + qb.z * kAb.z + qb.w * kAb.w;
        sA += __shfl_xor_sync(0xffffffffu, sA, 1);
        sA += __shfl_xor_sync(0xffffffffu, sA, 2);
        float mnA = fmaxf(mA, sA);
        float scA = __expf(mA - mnA);
        float pA = __expf(sA - mnA);
        lA = lA * scA + pA;
        oAa.x = fmaf(pA, vAa.x, oAa.x * scA); oAa.y = fmaf(pA, vAa.y, oAa.y * scA);
        oAa.z = fmaf(pA, vAa.z, oAa.z * scA); oAa.w = fmaf(pA, vAa.w, oAa.w * scA);
        oAb.x = fmaf(pA, vAb.x, oAb.x * scA); oAb.y = fmaf(pA, vAb.y, oAb.y * scA);
        oAb.z = fmaf(pA, vAb.z, oAb.z * scA); oAb.w = fmaf(pA, vAb.w, oAb.w * scA);
        mA = mnA;

        // stream B (t+1 may be past the end)
        float sB = qa.x * kBa.x + qa.y * kBa.y + qa.z * kBa.z + qa.w * kBa.w
                 + qb.x * kBb.x + qb.y * kBb.y + qb.z * kBb.z + qb.w * kBb.w;
        sB += __shfl_xor_sync(0xffffffffu, sB, 1);
        sB += __shfl_xor_sync(0xffffffffu, sB, 2);
        if (t + 1 >= cnt) sB = -INFINITY;
        float mnB = fmaxf(mB, sB);
        float scB = __expf(mB - mnB);
        float pB = __expf(sB - mnB);          // exp(-inf)=0 for padding
        lB = lB * scB + pB;
        oBa.x = fmaf(pB, vBa.x, oBa.x * scB); oBa.y = fmaf(pB, vBa.y, oBa.y * scB);
        oBa.z = fmaf(pB, vBa.z, oBa.z * scB); oBa.w = fmaf(pB, vBa.w, oBa.w * scB);
        oBb.x = fmaf(pB, vBb.x, oBb.x * scB); oBb.y = fmaf(pB, vBb.y, oBb.y * scB);
        oBb.z = fmaf(pB, vBb.z, oBb.z * scB); oBb.w = fmaf(pB, vBb.w, oBb.w * scB);
        mB = mnB;
    }

    // merge the two streams locally
    float m = fmaxf(mA, mB);
    float eA = __expf(mA - m), eB = __expf(mB - m);
    float l = lA * eA + lB * eB;
    float inv = 1.0f / (l + 1e-8f);
    float4 ra, rb;
    ra.x = (oAa.x * eA + oBa.x * eB) * inv; ra.y = (oAa.y * eA + oBa.y * eB) * inv;
    ra.z = (oAa.z * eA + oBa.z * eB) * inv; ra.w = (oAa.w * eA + oBa.w * eB) * inv;
    rb.x = (oAb.x * eA + oBb.x * eB) * inv; rb.y = (oAb.y * eA + oBb.y * eB) * inv;
    rb.z = (oAb.z * eA + oBb.z * eB) * inv; rb.w = (oAb.w * eA + oBb.w * eB) * inv;
    ((float4*)valp)[0] = ra;
    ((float4*)valp)[1] = rb;
}

// ---------------- 4) output projection  out = Wp @ val + b ------------------
// Scalar FFMA, 128(co) x 64(i) tile, 128 threads, 8x8 per thread, KC=32 with
// register-prefetch double buffering. Measured at the scalar-FFMA roofline.
#define PCO 128
#define PII 64
#define PKC 32
__global__ __launch_bounds__(128) void proj_kernel(const float* __restrict__ wp,
                                                   const float* __restrict__ bp,
                                                   float* __restrict__ out) {
    __shared__ float Ws[PKC][PCO + 4];   // [ci][co]
    __shared__ float Vs[PKC][PII + 4];   // [ci][i]
    int b = blockIdx.z;
    int coT = blockIdx.y * PCO;
    int iT = blockIdx.x * PII;
    int t = threadIdx.x;
    int tx = t & 7;                    // i group: tx*4 and tx*4+32
    int ty = t >> 3;                   // co group (0..15): ty*4 and ty*4+64
    int ci4 = (t & 7) * 4;             // load column group (0..28)
    int r0 = t >> 3;                   // load row base (0..15)

    float4 wpre[8], vpre[4];
#pragma unroll
    for (int p = 0; p < 8; p++)
        wpre[p] = *(const float4*)&wp[(size_t)(coT + r0 + p * 16) * CC + ci4];
#pragma unroll
    for (int p = 0; p < 4; p++) {
        int gi = iT + r0 + p * 16;
        vpre[p] = (gi < NN) ? *(const float4*)&g_val[((size_t)b * NN + gi) * CC + ci4]
                            : make_float4(0.f, 0.f, 0.f, 0.f);
    }

    float acc[8][8] = {};

    for (int kc = 0; kc < CC; kc += PKC) {
#pragma unroll
        for (int p = 0; p < 8; p++) {
            int r = r0 + p * 16;
            Ws[ci4 + 0][r] = wpre[p].x; Ws[ci4 + 1][r] = wpre[p].y;
            Ws[ci4 + 2][r] = wpre[p].z; Ws[ci4 + 3][r] = wpre[p].w;
        }
#pragma unroll
        for (int p = 0; p < 4; p++) {
            int io = r0 + p * 16;
            Vs[ci4 + 0][io] = vpre[p].x; Vs[ci4 + 1][io] = vpre[p].y;
            Vs[ci4 + 2][io] = vpre[p].z; Vs[ci4 + 3][io] = vpre[p].w;
        }
        __syncthreads();

        if (kc + PKC < CC) {
            int kcn = kc + PKC;
#pragma unroll
            for (int p = 0; p < 8; p++)
                wpre[p] = *(const float4*)&wp[(size_t)(coT + r0 + p * 16) * CC + kcn + ci4];
#pragma unroll
            for (int p = 0; p < 4; p++) {
                int gi = iT + r0 + p * 16;
                vpre[p] = (gi < NN) ? *(const float4*)&g_val[((size_t)b * NN + gi) * CC + kcn + ci4]
                                    : make_float4(0.f, 0.f, 0.f, 0.f);
            }
        }

#pragma unroll 8
        for (int ci = 0; ci < PKC; ci++) {
            float4 w0 = *(const float4*)&Ws[ci][ty * 4];
            float4 w1 = *(const float4*)&Ws[ci][64 + ty * 4];
            float4 v0 = *(const float4*)&Vs[ci][tx * 4];
            float4 v1 = *(const float4*)&Vs[ci][32 + tx * 4];
            float wr[8] = {w0.x, w0.y, w0.z, w0.w, w1.x, w1.y, w1.z, w1.w};
            float vr[8] = {v0.x, v0.y, v0.z, v0.w, v1.x, v1.y, v1.z, v1.w};
#pragma unroll
            for (int a = 0; a < 8; a++)
#pragma unroll
                for (int e = 0; e < 8; e++)
                    acc[a][e] = fmaf(wr[a], vr[e], acc[a][e]);
        }
        __syncthreads();
    }

#pragma unroll
    for (int a = 0; a < 8; a++) {
        int co = coT + (a < 4 ? (ty * 4 + a) : (64 + ty * 4 + (a - 4)));
        float bias = bp[co];
#pragma unroll
        for (int half = 0; half < 2; half++) {
            int gi = iT + (half == 0 ? tx * 4 : 32 + tx * 4);
            int e0 = half * 4;
            if (gi < NN) {   // NN % 4 == 0, whole float4 valid
                float4 r = make_float4(acc[a][e0 + 0] + bias, acc[a][e0 + 1] + bias,
                                       acc[a][e0 + 2] + bias, acc[a][e0 + 3] + bias);
                *(float4*)&out[((size_t)b * CC + co) * NN + gi] = r;
            }
        }
    }
}

// ---------------- launch ----------------------------------------------------
extern "C" void kernel_launch(void* const* d_in, const int* in_sizes, int n_in,
                              void* d_out, int out_size) {
    const float* queries = (const float*)d_in[0];
    const float* keys    = (const float*)d_in[1];
    const float* values  = (const float*)d_in[2];
    const float* boxes   = (const float*)d_in[3];
    const float* curmask = (const float*)d_in[4];
    const float* wq      = (const float*)d_in[5];
    const float* wk      = (const float*)d_in[6];
    const float* wv      = (const float*)d_in[7];
    const float* w_proj  = (const float*)d_in[8];
    const float* b_proj  = (const float*)d_in[9];
    float* out = (float*)d_out;

    sort_kernel<<<BS, 256>>>(boxes);
    mask_kernel<<<dim3(188, BS), 256>>>(boxes, curmask);
    qkv_kernel<<<dim3(6, BS * HH, 3), 256>>>(queries, keys, values, wq, wk, wv);
    attn_kernel<<<dim3((BS * NN + 3) / 4), 128>>>();
    proj_kernel<<<dim3((NN + PII - 1) / PII, CC / PCO, BS), 128>>>(w_proj, b_proj, out);
}

// round 8
// speedup vs baseline: 1.2695x; 1.1028x over previous
#include <cuda_runtime.h>
#include <math.h>

#define BS 8
#define CC 256
#define NN 1500
#define HH 8
#define DK 32

// ---------------- scratch (static device globals; no allocs) ----------------
// q/k/v stored head-interleaved: [b][n][h*DK]  (256 floats per token row)
__device__ float g_q[(size_t)BS * NN * CC];
__device__ float g_k[(size_t)BS * NN * CC];
__device__ float g_v[(size_t)BS * NN * CC];
__device__ float g_val[(size_t)BS * NN * CC];              // [b][n][c]
__device__ unsigned short g_nbr[(size_t)BS * NN * NN];     // per-row neighbor j lists
__device__ int g_cnt[BS * NN];
__device__ int g_perm[BS * NN];                            // spatial-sorted order

// ---------------- fused prep: sort (8) + mask (1504) + qkv (1152) -----------
#define SORT_BLKS 8
#define MASK_BLKS (188 * BS)
#define QKV_BLKS  (6 * BS * HH * 3)

__global__ __launch_bounds__(256) void prep_kernel(const float* __restrict__ boxes,
                                                   const float* __restrict__ cm,
                                                   const float* __restrict__ qin,
                                                   const float* __restrict__ kin,
                                                   const float* __restrict__ vin,
                                                   const float* __restrict__ wq,
                                                   const float* __restrict__ wk,
                                                   const float* __restrict__ wv) {
    __shared__ __align__(16) char sbuf[6 * NN * 4];   // 36000 B union
    int blk = blockIdx.x;
    int t = threadIdx.x;

    if (blk < SORT_BLKS) {
        // ----- spatial counting sort, one block per batch -----
        int* hist = (int*)sbuf;
        int* offs = hist + 64;
        int b = blk;
        if (t < 64) hist[t] = 0;
        __syncthreads();
        const float4* bb = (const float4*)(boxes + (size_t)b * NN * 4);
        for (int n = t; n < NN; n += 256) {
            float4 bx = bb[n];
            int kx = min(7, max(0, (int)(bx.x * 8.0f)));
            int ky = min(7, max(0, (int)(bx.y * 8.0f)));
            atomicAdd(&hist[kx * 8 + ky], 1);
        }
        __syncthreads();
        if (t == 0) {
            int run = 0;
            for (int k = 0; k < 64; k++) { offs[k] = run; run += hist[k]; }
        }
        __syncthreads();
        for (int n = t; n < NN; n += 256) {
            float4 bx = bb[n];
            int kx = min(7, max(0, (int)(bx.x * 8.0f)));
            int ky = min(7, max(0, (int)(bx.y * 8.0f)));
            int pos = atomicAdd(&offs[kx * 8 + ky], 1);
            g_perm[b * NN + pos] = n;
        }
        return;
    }

    if (blk < SORT_BLKS + MASK_BLKS) {
        // ----- mask + neighbor list, warp per query -----
        int u = blk - SORT_BLKS;
        int b = u / 188;
        int bx = u % 188;
        float* sx1 = (float*)sbuf;
        float* sy1 = sx1 + NN;
        float* sx2 = sy1 + NN;
        float* sy2 = sx2 + NN;
        float* sa  = sy2 + NN;
        float* scm = sa + NN;
        const float4* bb = (const float4*)(boxes + (size_t)b * NN * 4);
        for (int idx = t; idx < NN; idx += 256) {
            float4 bxv = bb[idx];
            float x1 = bxv.x - 0.5f * bxv.z;
            float x2 = bxv.x + 0.5f * bxv.z;
            float y1 = bxv.y - 0.5f * bxv.w;
            float y2 = bxv.y + 0.5f * bxv.w;
            sx1[idx] = x1; sx2[idx] = x2; sy1[idx] = y1; sy2[idx] = y2;
            sa[idx] = (x2 - x1) * (y2 - y1);
            scm[idx] = cm[(size_t)b * NN + idx];
        }
        __syncthreads();

        int warp = t >> 5, lane = t & 31;
        int i = bx * 8 + warp;
        if (i >= NN) return;
        float x1i = sx1[i], x2i = sx2[i], y1i = sy1[i], y2i = sy2[i];
        float ai = sa[i], cmi = scm[i];
        unsigned short* out = g_nbr + ((size_t)b * NN + i) * NN;
        int cnt = 0;
        for (int jb = 0; jb < NN; jb += 32) {
            int j = jb + lane;
            bool nbq = false;
            if (j < NN) {
                float ltx = fmaxf(x1i, sx1[j]);
                float lty = fmaxf(y1i, sy1[j]);
                float rbx = fminf(x2i, sx2[j]);
                float rby = fminf(y2i, sy2[j]);
                float iw = fmaxf(rbx - ltx, 0.0f);
                float ih = fmaxf(rby - lty, 0.0f);
                float inter = iw * ih;
                float uni = (ai + sa[j]) - inter;
                float prod = cmi * scm[j];
                if (prod == 1.0f) {
                    // exact predicate for fl_RN(inter/uni) > 0.5, no divide
                    float i2 = inter + inter;
                    if (i2 > uni * 1.00001f) nbq = true;
                    else if (i2 < uni * 0.99999f) nbq = false;
                    else nbq = ((double)inter >
                                (double)uni * 0.5000000298023223876953125);
                } else {
                    float iou = __fdiv_rn(inter, uni);
                    nbq = (iou * prod) > 0.5f;
                }
            }
            unsigned bal = __ballot_sync(0xffffffffu, nbq);
            int pos = cnt + __popc(bal & ((1u << lane) - 1u));
            if (nbq) out[pos] = (unsigned short)j;
            cnt += __popc(bal);
        }
        if (lane == 0) g_cnt[b * NN + i] = cnt;
        return;
    }

    // ----- qkv head projections -----
    {
        int u = blk - SORT_BLKS - MASK_BLKS;       // [0, 1152)
        int mat = u / (6 * BS * HH);
        int r = u % (6 * BS * HH);
        int bh = r / 6;
        int xc = r % 6;
        int b = bh >> 3, h = bh & 7;
        float4* sw = (float4*)sbuf;                 // 32x32 weights
        const float* W = (mat == 0 ? wq : (mat == 1 ? wk : wv)) + h * DK * DK;
        const float* X = (mat == 0 ? qin : (mat == 1 ? kin : vin));
        float* O = (mat == 0 ? g_q : (mat == 1 ? g_k : g_v));
        sw[t] = ((const float4*)W)[t];
        __syncthreads();

        int i = xc * 256 + t;
        if (i >= NN) return;
        float x[DK];
        const float* xp = X + ((size_t)b * CC + h * DK) * NN + i;
#pragma unroll
        for (int j = 0; j < DK; j++) x[j] = xp[(size_t)j * NN];

        float out[DK];
#pragma unroll
        for (int d = 0; d < DK; d++) {
            float acc = 0.0f;
#pragma unroll
            for (int jq = 0; jq < 8; jq++) {
                float4 w4 = sw[d * 8 + jq];
                acc = fmaf(w4.x, x[jq * 4 + 0], acc);
                acc = fmaf(w4.y, x[jq * 4 + 1], acc);
                acc = fmaf(w4.z, x[jq * 4 + 2], acc);
                acc = fmaf(w4.w, x[jq * 4 + 3], acc);
            }
            out[d] = acc;
        }
        float4* op = (float4*)(O + ((size_t)b * NN + i) * CC + h * DK);
#pragma unroll
        for (int rr = 0; rr < 8; rr++)
            op[rr] = make_float4(out[rr * 4], out[rr * 4 + 1],
                                 out[rr * 4 + 2], out[rr * 4 + 3]);
    }
}

// ---------------- sparse masked attention (warp per query, ALL heads) -------
// Layout v2: lane L owns dims [4L,4L+4) of head L>>3 and [128+4L,128+4L+4) of
// head 4+(L>>3). Every LDG.128 is lane-contiguous (512B/instr = 4 lines), so
// k/v row wavefronts are halved vs the strided-slice layout. Dot reduction is
// 3 shfls over 8 lanes, done for two heads per lane; each lane runs two
// independent per-head online-softmax streams (no cross-lane merge needed).
__device__ __forceinline__ void os_update(float& m, float& l, float4& o,
                                          float s, const float4& v) {
    float mn = fmaxf(m, s);
    float sc = __expf(m - mn);
    float p = __expf(s - mn);        // s==-inf (padding) -> p=0
    l = l * sc + p;
    o.x = fmaf(p, v.x, o.x * sc);
    o.y = fmaf(p, v.y, o.y * sc);
    o.z = fmaf(p, v.z, o.z * sc);
    o.w = fmaf(p, v.w, o.w * sc);
    m = mn;
}

__global__ __launch_bounds__(256, 3) void attn_kernel() {
    int warp = threadIdx.x >> 5, lane = threadIdx.x & 31;
    int gs = blockIdx.x * 8 + warp;          // sorted rank within b*NN
    if (gs >= BS * NN) return;
    int b = gs / NN;
    int gi = b * NN + g_perm[gs];            // actual b*NN + i

    int cnt = g_cnt[gi];
    size_t rowq = (size_t)gi * CC;
    int lo = 4 * lane, hi = 128 + 4 * lane;
    const float* kbase = g_k + (size_t)b * NN * CC;
    const float* vbase = g_v + (size_t)b * NN * CC;
    float* valr = g_val + rowq;

    if (cnt == 0) {   // has_nb == 0 fallback: val = v
        const float* vr = g_v + rowq;
        *(float4*)(valr + lo) = *(const float4*)(vr + lo);
        *(float4*)(valr + hi) = *(const float4*)(vr + hi);
        return;
    }

    float4 q0 = *(const float4*)(g_q + rowq + lo);
    float4 q1 = *(const float4*)(g_q + rowq + hi);
    const unsigned short* nb = g_nbr + (size_t)gi * NN;
    int cm1 = cnt - 1;

    // reference: max_val = max(attn * mask) -> masked zeros participate in max
    float minit = (cnt < NN) ? 0.0f : -INFINITY;
    float m0 = minit, m1 = minit, l0 = 0.f, l1 = 0.f;
    float4 o0 = {0,0,0,0}, o1 = {0,0,0,0};

#define R8(s) s += __shfl_xor_sync(0xffffffffu, s, 1); \
              s += __shfl_xor_sync(0xffffffffu, s, 2); \
              s += __shfl_xor_sync(0xffffffffu, s, 4);

    for (int t = 0; t < cnt; t += 2) {
        int jA = nb[t], jB = nb[min(t + 1, cm1)];
        const float* kA = kbase + (size_t)jA * CC;
        const float* vA = vbase + (size_t)jA * CC;
        const float* kB = kbase + (size_t)jB * CC;
        const float* vB = vbase + (size_t)jB * CC;
        float4 kA0 = *(const float4*)(kA + lo), kA1 = *(const float4*)(kA + hi);
        float4 vA0 = *(const float4*)(vA + lo), vA1 = *(const float4*)(vA + hi);
        float4 kB0 = *(const float4*)(kB + lo), kB1 = *(const float4*)(kB + hi);
        float4 vB0 = *(const float4*)(vB + lo), vB1 = *(const float4*)(vB + hi);

        float sA0 = q0.x * kA0.x + q0.y * kA0.y + q0.z * kA0.z + q0.w * kA0.w;
        float sA1 = q1.x * kA1.x + q1.y * kA1.y + q1.z * kA1.z + q1.w * kA1.w;
        float sB0 = q0.x * kB0.x + q0.y * kB0.y + q0.z * kB0.z + q0.w * kB0.w;
        float sB1 = q1.x * kB1.x + q1.y * kB1.y + q1.z * kB1.z + q1.w * kB1.w;
        R8(sA0) R8(sA1) R8(sB0) R8(sB1)
        if (t + 1 >= cnt) { sB0 = -INFINITY; sB1 = -INFINITY; }

        os_update(m0, l0, o0, sA0, vA0);
        os_update(m0, l0, o0, sB0, vB0);
        os_update(m1, l1, o1, sA1, vA1);
        os_update(m1, l1, o1, sB1, vB1);
    }
#undef R8

    float inv0 = 1.0f / (l0 + 1e-8f);
    float inv1 = 1.0f / (l1 + 1e-8f);
    *(float4*)(valr + lo) = make_float4(o0.x * inv0, o0.y * inv0,
                                        o0.z * inv0, o0.w * inv0);
    *(float4*)(valr + hi) = make_float4(o1.x * inv1, o1.y * inv1,
                                        o1.z * inv1, o1.w * inv1);
}

// ---------------- output projection  out = Wp @ val + b ---------------------
// Scalar FFMA, 128(co) x 64(i) tile, 128 threads, 8x8 per thread, KC=32 with
// register-prefetch double buffering. Measured at the scalar-FFMA roofline.
#define PCO 128
#define PII 64
#define PKC 32
__global__ __launch_bounds__(128) void proj_kernel(const float* __restrict__ wp,
                                                   const float* __restrict__ bp,
                                                   float* __restrict__ out) {
    __shared__ float Ws[PKC][PCO + 4];   // [ci][co]
    __shared__ float Vs[PKC][PII + 4];   // [ci][i]
    int b = blockIdx.z;
    int coT = blockIdx.y * PCO;
    int iT = blockIdx.x * PII;
    int t = threadIdx.x;
    int tx = t & 7;                    // i group: tx*4 and tx*4+32
    int ty = t >> 3;                   // co group (0..15): ty*4 and ty*4+64
    int ci4 = (t & 7) * 4;             // load column group (0..28)
    int r0 = t >> 3;                   // load row base (0..15)

    float4 wpre[8], vpre[4];
#pragma unroll
    for (int p = 0; p < 8; p++)
        wpre[p] = *(const float4*)&wp[(size_t)(coT + r0 + p * 16) * CC + ci4];
#pragma unroll
    for (int p = 0; p < 4; p++) {
        int gi = iT + r0 + p * 16;
        vpre[p] = (gi < NN) ? *(const float4*)&g_val[((size_t)b * NN + gi) * CC + ci4]
                            : make_float4(0.f, 0.f, 0.f, 0.f);
    }

    float acc[8][8] = {};

    for (int kc = 0; kc < CC; kc += PKC) {
#pragma unroll
        for (int p = 0; p < 8; p++) {
            int r = r0 + p * 16;
            Ws[ci4 + 0][r] = wpre[p].x; Ws[ci4 + 1][r] = wpre[p].y;
            Ws[ci4 + 2][r] = wpre[p].z; Ws[ci4 + 3][r] = wpre[p].w;
        }
#pragma unroll
        for (int p = 0; p < 4; p++) {
            int io = r0 + p * 16;
            Vs[ci4 + 0][io] = vpre[p].x; Vs[ci4 + 1][io] = vpre[p].y;
            Vs[ci4 + 2][io] = vpre[p].z; Vs[ci4 + 3][io] = vpre[p].w;
        }
        __syncthreads();

        if (kc + PKC < CC) {
            int kcn = kc + PKC;
#pragma unroll
            for (int p = 0; p < 8; p++)
                wpre[p] = *(const float4*)&wp[(size_t)(coT + r0 + p * 16) * CC + kcn + ci4];
#pragma unroll
            for (int p = 0; p < 4; p++) {
                int gi = iT + r0 + p * 16;
                vpre[p] = (gi < NN) ? *(const float4*)&g_val[((size_t)b * NN + gi) * CC + kcn + ci4]
                                    : make_float4(0.f, 0.f, 0.f, 0.f);
            }
        }

#pragma unroll 8
        for (int ci = 0; ci < PKC; ci++) {
            float4 w0 = *(const float4*)&Ws[ci][ty * 4];
            float4 w1 = *(const float4*)&Ws[ci][64 + ty * 4];
            float4 v0 = *(const float4*)&Vs[ci][tx * 4];
            float4 v1 = *(const float4*)&Vs[ci][32 + tx * 4];
            float wr[8] = {w0.x, w0.y, w0.z, w0.w, w1.x, w1.y, w1.z, w1.w};
            float vr[8] = {v0.x, v0.y, v0.z, v0.w, v1.x, v1.y, v1.z, v1.w};
#pragma unroll
            for (int a = 0; a < 8; a++)
#pragma unroll
                for (int e = 0; e < 8; e++)
                    acc[a][e] = fmaf(wr[a], vr[e], acc[a][e]);
        }
        __syncthreads();
    }

#pragma unroll
    for (int a = 0; a < 8; a++) {
        int co = coT + (a < 4 ? (ty * 4 + a) : (64 + ty * 4 + (a - 4)));
        float bias = bp[co];
#pragma unroll
        for (int half = 0; half < 2; half++) {
            int gi = iT + (half == 0 ? tx * 4 : 32 + tx * 4);
            int e0 = half * 4;
            if (gi < NN) {   // NN % 4 == 0, whole float4 valid
                float4 r = make_float4(acc[a][e0 + 0] + bias, acc[a][e0 + 1] + bias,
                                       acc[a][e0 + 2] + bias, acc[a][e0 + 3] + bias);
                *(float4*)&out[((size_t)b * CC + co) * NN + gi] = r;
            }
        }
    }
}

// ---------------- launch ----------------------------------------------------
extern "C" void kernel_launch(void* const* d_in, const int* in_sizes, int n_in,
                              void* d_out, int out_size) {
    const float* queries = (const float*)d_in[0];
    const float* keys    = (const float*)d_in[1];
    const float* values  = (const float*)d_in[2];
    const float* boxes   = (const float*)d_in[3];
    const float* curmask = (const float*)d_in[4];
    const float* wq      = (const float*)d_in[5];
    const float* wk      = (const float*)d_in[6];
    const float* wv      = (const float*)d_in[7];
    const float* w_proj  = (const float*)d_in[8];
    const float* b_proj  = (const float*)d_in[9];
    float* out = (float*)d_out;

    prep_kernel<<<SORT_BLKS + MASK_BLKS + QKV_BLKS, 256>>>(
        boxes, curmask, queries, keys, values, wq, wk, wv);
    attn_kernel<<<dim3((BS * NN + 7) / 8), 256>>>();
    proj_kernel<<<dim3((NN + PII - 1) / PII, CC / PCO, BS), 128>>>(w_proj, b_proj, out);
}